// round 3
// baseline (speedup 1.0000x reference)
#include <cuda_runtime.h>
#include <cuda_bf16.h>

// Shapes (fixed per reference)
#define B_SZ     8192
#define K_SZ     50
#define KG_DIM   64
#define IN_SZ    512
#define CC       64
#define OUT_SZ   1024

// ---------------------------------------------------------------------------
// Scratch (static device globals -- no runtime allocation allowed)
// ---------------------------------------------------------------------------
__device__ float g_h1[B_SZ * 128];
__device__ float g_h2[B_SZ * 512];
__device__ float g_h3[B_SZ * 128];
__device__ float g_h4[B_SZ * CC];
__device__ float g_know[B_SZ * CC];
__device__ int   g_cnt[B_SZ];
__device__ int   g_cidx[B_SZ * K_SZ];

// ---------------------------------------------------------------------------
// Kernel 1: warp-per-row compaction of masked gather indices.
// mask ~ Bernoulli(0.5) -> halves the knowledge-branch FLOPs downstream.
// ---------------------------------------------------------------------------
__global__ void __launch_bounds__(256) compact_kernel(
    const int* __restrict__ idx, const int* __restrict__ mask,
    int* __restrict__ cidx, int* __restrict__ cnt)
{
    int b = blockIdx.x * (blockDim.x >> 5) + (threadIdx.x >> 5);
    if (b >= B_SZ) return;
    int l = threadIdx.x & 31;
    int base = b * K_SZ;
    int c = 0;
    #pragma unroll
    for (int k0 = 0; k0 < K_SZ; k0 += 32) {
        int k = k0 + l;
        bool m = (k < K_SZ) && (mask[base + k] != 0);
        unsigned bal = __ballot_sync(0xffffffffu, m);
        int pos = c + __popc(bal & ((1u << l) - 1u));
        if (m) cidx[base + pos] = idx[base + k];
        c += __popc(bal);
    }
    if (l == 0) cnt[b] = c;
}

// ---------------------------------------------------------------------------
// Kernel 2: knowledge branch.
//   knowledge[b][c] = sum_j relu( kg[cidx[b][j]] . Wkg[:,c] + bkg[c] )
// Block = 256 threads = 8 warps, handles 4 batch rows (2 warps per row,
// splitting the j loop). Wkg (16KB) resident in smem, amortized over 4 rows.
// Per warp: lane owns 2 output columns (float2 W reads), gather row staged in
// smem (per-warp slot, __syncwarp only -> no cross-warp lockstep needed).
// ---------------------------------------------------------------------------
__global__ void __launch_bounds__(256) knowledge_kernel(
    const float* __restrict__ kg, const float* __restrict__ Wkg,
    const float* __restrict__ bkg, const int* __restrict__ cidx,
    const int* __restrict__ cnt, float* __restrict__ know)
{
    __shared__ float Ws[KG_DIM * CC];     // Wkg[d][c], 16 KB
    __shared__ float sg[8][KG_DIM];       // per-warp gathered row
    __shared__ float kacc[4][CC];         // per-local-batch accumulator

    int tid = threadIdx.x;

    // cooperative Wkg load (float4)
    for (int i = tid * 4; i < KG_DIM * CC; i += 256 * 4)
        *(float4*)&Ws[i] = *(const float4*)&Wkg[i];
    ((float*)kacc)[tid] = 0.f;            // 4*64 = 256 values
    __syncthreads();

    int w  = tid >> 5;
    int l  = tid & 31;
    int bl = w >> 1;                      // local batch 0..3
    int jo = w & 1;                       // j phase within pair
    int b  = blockIdx.x * 4 + bl;
    int c0 = l * 2;

    float bb0 = bkg[c0], bb1 = bkg[c0 + 1];
    float acc0 = 0.f, acc1 = 0.f;

    int n = cnt[b];
    const int* cp = cidx + b * K_SZ;

    for (int j = jo; j < n; j += 2) {
        int row = cp[j];
        const float* gp = kg + (long)row * KG_DIM;
        sg[w][l]      = gp[l];
        sg[w][l + 32] = gp[l + 32];
        __syncwarp();

        float s0 = bb0, s1 = bb1;
        #pragma unroll
        for (int d = 0; d < KG_DIM; d += 4) {
            float4 g4 = *(const float4*)&sg[w][d];
            float2 w0 = *(const float2*)&Ws[(d + 0) * CC + c0];
            float2 w1 = *(const float2*)&Ws[(d + 1) * CC + c0];
            float2 w2 = *(const float2*)&Ws[(d + 2) * CC + c0];
            float2 w3 = *(const float2*)&Ws[(d + 3) * CC + c0];
            s0 = fmaf(g4.x, w0.x, s0); s1 = fmaf(g4.x, w0.y, s1);
            s0 = fmaf(g4.y, w1.x, s0); s1 = fmaf(g4.y, w1.y, s1);
            s0 = fmaf(g4.z, w2.x, s0); s1 = fmaf(g4.z, w2.y, s1);
            s0 = fmaf(g4.w, w3.x, s0); s1 = fmaf(g4.w, w3.y, s1);
        }
        acc0 += fmaxf(s0, 0.f);
        acc1 += fmaxf(s1, 0.f);
        __syncwarp();                     // protect sg before next overwrite
    }

    atomicAdd(&kacc[bl][c0],     acc0);
    atomicAdd(&kacc[bl][c0 + 1], acc1);
    __syncthreads();

    int ob = tid >> 6, oc = tid & 63;
    know[(blockIdx.x * 4 + ob) * CC + oc] = kacc[ob][oc];
}

// ---------------------------------------------------------------------------
// Kernel 3: tiled SGEMM  C = act(A @ W + bias) [+ addk]
// A: [M,K] row-major, W: [K,N] row-major, C: [M,N].
// BM=128, BN=64, BK=16, 256 threads, 8x4 register tile (32 accumulators).
// RELU: apply max(.,0); ADDK: C = relu(A@W+b) + addk  (knowledge fusion).
// All shapes here are exact multiples of the tile -> no bounds checks.
// ---------------------------------------------------------------------------
#define BM 128
#define BN 64
#define BKD 16
#define AS_LD 132   // padded stride: conflict-reduced transpose stores, float4-aligned

template <bool RELU, bool ADDK>
__global__ void __launch_bounds__(256) gemm_kernel(
    const float* __restrict__ A, const float* __restrict__ W,
    const float* __restrict__ bias, const float* __restrict__ addk,
    float* __restrict__ C, int M, int N, int K)
{
    __shared__ float As[BKD * AS_LD];   // transposed: As[k][m]
    __shared__ float Bs[BKD * BN];      // Bs[k][n]

    int tid = threadIdx.x;
    int m0 = blockIdx.y * BM;
    int n0 = blockIdx.x * BN;

    // A tile load mapping: 128 rows x 16 cols, 2 float4 per thread
    int a_row = tid >> 2;               // 0..63
    int a_col = (tid & 3) * 4;          // 0,4,8,12
    // B tile load mapping: 16 rows x 64 cols, 1 float4 per thread
    int b_row = tid >> 4;               // 0..15
    int b_col = (tid & 15) * 4;         // 0..60

    // compute mapping: 16(ty, m-dir) x 16(tx, n-dir)
    int ty = tid >> 4, tx = tid & 15;
    int mb = ty * 8, nb = tx * 4;

    float acc[8][4];
    #pragma unroll
    for (int i = 0; i < 8; i++)
        #pragma unroll
        for (int j = 0; j < 4; j++) acc[i][j] = 0.f;

    const float* Ap = A + (long)(m0 + a_row) * K + a_col;
    const float* Bp = W + (long)b_row * N + n0 + b_col;

    for (int kt = 0; kt < K; kt += BKD) {
        float4 av0 = *(const float4*)(Ap);
        float4 av1 = *(const float4*)(Ap + (long)64 * K);
        float4 bv  = *(const float4*)(Bp);
        Ap += BKD;
        Bp += (long)BKD * N;

        As[(a_col + 0) * AS_LD + a_row] = av0.x;
        As[(a_col + 1) * AS_LD + a_row] = av0.y;
        As[(a_col + 2) * AS_LD + a_row] = av0.z;
        As[(a_col + 3) * AS_LD + a_row] = av0.w;
        As[(a_col + 0) * AS_LD + a_row + 64] = av1.x;
        As[(a_col + 1) * AS_LD + a_row + 64] = av1.y;
        As[(a_col + 2) * AS_LD + a_row + 64] = av1.z;
        As[(a_col + 3) * AS_LD + a_row + 64] = av1.w;
        *(float4*)&Bs[b_row * BN + b_col] = bv;
        __syncthreads();

        #pragma unroll
        for (int k = 0; k < BKD; k++) {
            float a[8], bq[4];
            *(float4*)&a[0]  = *(const float4*)&As[k * AS_LD + mb];
            *(float4*)&a[4]  = *(const float4*)&As[k * AS_LD + mb + 4];
            *(float4*)&bq[0] = *(const float4*)&Bs[k * BN + nb];
            #pragma unroll
            for (int i = 0; i < 8; i++)
                #pragma unroll
                for (int j = 0; j < 4; j++)
                    acc[i][j] = fmaf(a[i], bq[j], acc[i][j]);
        }
        __syncthreads();
    }

    float bias4[4];
    *(float4*)&bias4[0] = *(const float4*)&bias[n0 + nb];

    #pragma unroll
    for (int i = 0; i < 8; i++) {
        int m = m0 + mb + i;
        float v[4];
        #pragma unroll
        for (int j = 0; j < 4; j++) {
            float t = acc[i][j] + bias4[j];
            if (RELU) t = fmaxf(t, 0.f);
            v[j] = t;
        }
        if (ADDK) {
            float kv[4];
            *(float4*)&kv[0] = *(const float4*)&addk[(long)m * N + n0 + nb];
            #pragma unroll
            for (int j = 0; j < 4; j++) v[j] += kv[j];
        }
        *(float4*)&C[(long)m * N + n0 + nb] = *(float4*)&v[0];
    }
}

// ---------------------------------------------------------------------------
// Launcher
// Input order (metadata): x, kg, idx, mask, Wkg, bkg, W1a,b1a, W1b,b1b,
//                         W1c,b1c, W1d,b1d, W2,b2.  Output: float [8192,1024].
// ---------------------------------------------------------------------------
extern "C" void kernel_launch(void* const* d_in, const int* in_sizes, int n_in,
                              void* d_out, int out_size)
{
    const float* x    = (const float*)d_in[0];
    const float* kg   = (const float*)d_in[1];
    const int*   idx  = (const int*)  d_in[2];
    const int*   mask = (const int*)  d_in[3];
    const float* Wkg  = (const float*)d_in[4];
    const float* bkg  = (const float*)d_in[5];
    const float* W1a  = (const float*)d_in[6];
    const float* b1a  = (const float*)d_in[7];
    const float* W1b  = (const float*)d_in[8];
    const float* b1b  = (const float*)d_in[9];
    const float* W1c  = (const float*)d_in[10];
    const float* b1c  = (const float*)d_in[11];
    const float* W1d  = (const float*)d_in[12];
    const float* b1d  = (const float*)d_in[13];
    const float* W2   = (const float*)d_in[14];
    const float* b2   = (const float*)d_in[15];
    float* out = (float*)d_out;

    float *h1, *h2, *h3, *h4, *know;
    int *cnt, *cidx;
    cudaGetSymbolAddress((void**)&h1,   g_h1);
    cudaGetSymbolAddress((void**)&h2,   g_h2);
    cudaGetSymbolAddress((void**)&h3,   g_h3);
    cudaGetSymbolAddress((void**)&h4,   g_h4);
    cudaGetSymbolAddress((void**)&know, g_know);
    cudaGetSymbolAddress((void**)&cnt,  g_cnt);
    cudaGetSymbolAddress((void**)&cidx, g_cidx);

    // knowledge branch
    compact_kernel<<<B_SZ / 8, 256>>>(idx, mask, cidx, cnt);
    knowledge_kernel<<<B_SZ / 4, 256>>>(kg, Wkg, bkg, cidx, cnt, know);

    // dense MLP chain (runs after compact/knowledge in-stream; independent of
    // them until the ADDK fusion at layer 1d)
    gemm_kernel<true, false><<<dim3(128 / BN,  B_SZ / BM), 256>>>(
        x,  W1a, b1a, nullptr, h1, B_SZ, 128, IN_SZ);
    gemm_kernel<true, false><<<dim3(512 / BN,  B_SZ / BM), 256>>>(
        h1, W1b, b1b, nullptr, h2, B_SZ, 512, 128);
    gemm_kernel<true, false><<<dim3(128 / BN,  B_SZ / BM), 256>>>(
        h2, W1c, b1c, nullptr, h3, B_SZ, 128, 512);
    // h4 = relu(h3 @ W1d + b1d) + knowledge   (fused)
    gemm_kernel<true, true><<<dim3(CC / BN,    B_SZ / BM), 256>>>(
        h3, W1d, b1d, know, h4, B_SZ, CC, 128);
    // out = h4 @ W2 + b2
    gemm_kernel<false, false><<<dim3(OUT_SZ / BN, B_SZ / BM), 256>>>(
        h4, W2, b2, nullptr, out, B_SZ, OUT_SZ, CC);
}

// round 6
// speedup vs baseline: 1.8474x; 1.8474x over previous
#include <cuda_runtime.h>
#include <cuda_bf16.h>

// Shapes (fixed per reference)
#define B_SZ     8192
#define K_SZ     50
#define KG_DIM   64
#define IN_SZ    512
#define CC       64
#define OUT_SZ   1024

// ---------------------------------------------------------------------------
// Scratch (static device globals -- no runtime allocation allowed)
// ---------------------------------------------------------------------------
__device__ float g_h1[B_SZ * 128];
__device__ float g_h2[B_SZ * 512];
__device__ float g_h3[B_SZ * 128];
__device__ float g_h4[B_SZ * CC];
__device__ float g_know[B_SZ * CC];
__device__ int   g_cnt[B_SZ];
__device__ int   g_cidx[B_SZ * K_SZ];

// ---------------------------------------------------------------------------
// Kernel 1: warp-per-row compaction of masked gather indices.
// mask ~ Bernoulli(0.5) -> halves the knowledge-branch FLOPs downstream.
// ---------------------------------------------------------------------------
__global__ void __launch_bounds__(256) compact_kernel(
    const int* __restrict__ idx, const int* __restrict__ mask,
    int* __restrict__ cidx, int* __restrict__ cnt)
{
    int b = blockIdx.x * (blockDim.x >> 5) + (threadIdx.x >> 5);
    if (b >= B_SZ) return;
    int l = threadIdx.x & 31;
    int base = b * K_SZ;
    int c = 0;
    #pragma unroll
    for (int k0 = 0; k0 < K_SZ; k0 += 32) {
        int k = k0 + l;
        bool m = (k < K_SZ) && (mask[base + k] != 0);
        unsigned bal = __ballot_sync(0xffffffffu, m);
        int pos = c + __popc(bal & ((1u << l) - 1u));
        if (m) cidx[base + pos] = idx[base + k];
        c += __popc(bal);
    }
    if (l == 0) cnt[b] = c;
}

// ---------------------------------------------------------------------------
// Kernel 2: knowledge branch (v2 -- register-resident Wkg).
//   knowledge[b][c] = sum_j relu( kg[cidx[b][j]] . Wkg[:,c] + bkg[c] )
//
// Block = 256 threads = 8 warps = 4 warp-PAIRS. Each pair owns KB_PW batches;
// within a pair, warp 0 covers columns 0..31, warp 1 covers 32..63 (1 column
// per lane). Each lane keeps its Wkg column (64 floats) in REGISTERS.
// The gathered kg row is double-buffered in smem (per-warp slot): the warp
// prefetches row j+1 (float2/lane LDG) while computing row j via broadcast
// LDS.128 reads. 4 rotating partial sums -> fully pipelined FFMA chain.
// Result store is direct (each (b,c) owned by exactly one lane).
// ---------------------------------------------------------------------------
#define KB_PW 4
__global__ void __launch_bounds__(256) knowledge_kernel(
    const float* __restrict__ kg, const float* __restrict__ Wkg,
    const float* __restrict__ bkg, const int* __restrict__ cidx,
    const int* __restrict__ cnt, float* __restrict__ know)
{
    __shared__ float sg[8][2][KG_DIM];     // per-warp double-buffered row

    int tid = threadIdx.x;
    int w   = tid >> 5;
    int l   = tid & 31;
    int pr  = w >> 1;                      // warp-pair 0..3
    int hf  = w & 1;                       // column half
    int c   = hf * 32 + l;                 // owned column

    float Wr[KG_DIM];
    #pragma unroll
    for (int d = 0; d < KG_DIM; d++) Wr[d] = Wkg[d * CC + c];
    float bc = bkg[c];

    for (int bi = 0; bi < KB_PW; bi++) {
        int b = (blockIdx.x * 4 + pr) * KB_PW + bi;
        int n = cnt[b];
        const int* cp = cidx + b * K_SZ;
        float acc = 0.f;

        if (n > 0) {
            int r = cp[0];
            float2 g2 = *(const float2*)(kg + (long)r * KG_DIM + 2 * l);
            *(float2*)&sg[w][0][2 * l] = g2;
        }
        __syncwarp();

        for (int j = 0; j < n; j++) {
            int buf = j & 1;
            float2 nx;
            bool more = (j + 1 < n);
            if (more) {
                int r2 = cp[j + 1];
                nx = *(const float2*)(kg + (long)r2 * KG_DIM + 2 * l);
            }
            float s0 = bc, s1 = 0.f, s2 = 0.f, s3 = 0.f;
            #pragma unroll
            for (int d = 0; d < KG_DIM; d += 4) {
                float4 g4 = *(const float4*)&sg[w][buf][d];   // broadcast
                s0 = fmaf(g4.x, Wr[d + 0], s0);
                s1 = fmaf(g4.y, Wr[d + 1], s1);
                s2 = fmaf(g4.z, Wr[d + 2], s2);
                s3 = fmaf(g4.w, Wr[d + 3], s3);
            }
            float s = (s0 + s1) + (s2 + s3);
            acc += fmaxf(s, 0.f);
            if (more) *(float2*)&sg[w][buf ^ 1][2 * l] = nx;
            __syncwarp();
        }
        know[(long)b * CC + c] = acc;
    }
}

// ---------------------------------------------------------------------------
// Kernel 3: double-buffered tiled SGEMM  C = act(A @ W + bias) [+ addk]
// A: [M,K] row-major, W: [K,N] row-major, C: [M,N].  BN=64 fixed, 256 threads.
// Config A: BM=128, BK=16, TM=8 (8x4 thread tile)  -- wide-N layers
// Config B: BM=64,  BK=32, TM=4 (4x4 thread tile)  -- N=128/64 layers (more blocks)
// Global loads for tile k+1 are issued into registers before computing tile k.
// All shapes are exact tile multiples -> no bounds checks.
// ---------------------------------------------------------------------------
template <int BM_, int BK_, int TM_, bool RELU, bool ADDK>
__global__ void __launch_bounds__(256) gemm_kernel(
    const float* __restrict__ A, const float* __restrict__ W,
    const float* __restrict__ bias, const float* __restrict__ addk,
    float* __restrict__ C, int M, int N, int K)
{
    constexpr int BN_  = 64;
    constexpr int ALD  = BM_ + 4;              // padded transposed-A stride
    constexpr int A_PT = (BM_ * BK_ / 4) / 256; // float4 per thread (A tile) = 2
    constexpr int B_PT = (BK_ * BN_ / 4) / 256; // float4 per thread (B tile) = 1 or 2
    constexpr int ACOLS4 = BK_ / 4;

    __shared__ float As[2][BK_ * ALD];          // transposed: As[k][m]
    __shared__ float Bs[2][BK_ * BN_];          // Bs[k][n]

    int tid = threadIdx.x;
    int m0 = blockIdx.y * BM_;
    int n0 = blockIdx.x * BN_;

    // load mappings
    int a_row[A_PT], a_col[A_PT];
    const float* Ap[A_PT];
    #pragma unroll
    for (int t = 0; t < A_PT; t++) {
        int id = tid + t * 256;
        a_row[t] = id / ACOLS4;
        a_col[t] = (id % ACOLS4) * 4;
        Ap[t] = A + (long)(m0 + a_row[t]) * K + a_col[t];
    }
    int b_row[B_PT], b_col[B_PT];
    const float* Bp[B_PT];
    #pragma unroll
    for (int t = 0; t < B_PT; t++) {
        int id = tid + t * 256;
        b_row[t] = id >> 4;
        b_col[t] = (id & 15) * 4;
        Bp[t] = W + (long)b_row[t] * N + n0 + b_col[t];
    }

    // compute mapping: 16(ty, m) x 16(tx, n)
    int ty = tid >> 4, tx = tid & 15;
    int mb = ty * TM_, nb = tx * 4;

    float acc[TM_][4];
    #pragma unroll
    for (int i = 0; i < TM_; i++)
        #pragma unroll
        for (int j = 0; j < 4; j++) acc[i][j] = 0.f;

    float4 pa[A_PT], pb[B_PT];

    // preload tile 0
    #pragma unroll
    for (int t = 0; t < A_PT; t++) { pa[t] = *(const float4*)Ap[t]; Ap[t] += BK_; }
    #pragma unroll
    for (int t = 0; t < B_PT; t++) { pb[t] = *(const float4*)Bp[t]; Bp[t] += (long)BK_ * N; }
    #pragma unroll
    for (int t = 0; t < A_PT; t++) {
        As[0][(a_col[t] + 0) * ALD + a_row[t]] = pa[t].x;
        As[0][(a_col[t] + 1) * ALD + a_row[t]] = pa[t].y;
        As[0][(a_col[t] + 2) * ALD + a_row[t]] = pa[t].z;
        As[0][(a_col[t] + 3) * ALD + a_row[t]] = pa[t].w;
    }
    #pragma unroll
    for (int t = 0; t < B_PT; t++)
        *(float4*)&Bs[0][b_row[t] * BN_ + b_col[t]] = pb[t];
    __syncthreads();

    int nt = K / BK_;
    for (int kt = 0; kt < nt; kt++) {
        int cur = kt & 1;
        bool more = (kt + 1 < nt);
        if (more) {
            #pragma unroll
            for (int t = 0; t < A_PT; t++) { pa[t] = *(const float4*)Ap[t]; Ap[t] += BK_; }
            #pragma unroll
            for (int t = 0; t < B_PT; t++) { pb[t] = *(const float4*)Bp[t]; Bp[t] += (long)BK_ * N; }
        }

        const float* Asc = As[cur];
        const float* Bsc = Bs[cur];
        #pragma unroll
        for (int k = 0; k < BK_; k++) {
            float a[TM_], bq[4];
            #pragma unroll
            for (int i = 0; i < TM_; i += 4)
                *(float4*)&a[i] = *(const float4*)&Asc[k * ALD + mb + i];
            *(float4*)&bq[0] = *(const float4*)&Bsc[k * BN_ + nb];
            #pragma unroll
            for (int i = 0; i < TM_; i++)
                #pragma unroll
                for (int j = 0; j < 4; j++)
                    acc[i][j] = fmaf(a[i], bq[j], acc[i][j]);
        }

        if (more) {
            int nxt = cur ^ 1;
            #pragma unroll
            for (int t = 0; t < A_PT; t++) {
                As[nxt][(a_col[t] + 0) * ALD + a_row[t]] = pa[t].x;
                As[nxt][(a_col[t] + 1) * ALD + a_row[t]] = pa[t].y;
                As[nxt][(a_col[t] + 2) * ALD + a_row[t]] = pa[t].z;
                As[nxt][(a_col[t] + 3) * ALD + a_row[t]] = pa[t].w;
            }
            #pragma unroll
            for (int t = 0; t < B_PT; t++)
                *(float4*)&Bs[nxt][b_row[t] * BN_ + b_col[t]] = pb[t];
            __syncthreads();
        }
    }

    float bias4[4];
    *(float4*)&bias4[0] = *(const float4*)&bias[n0 + nb];

    #pragma unroll
    for (int i = 0; i < TM_; i++) {
        int m = m0 + mb + i;
        float v[4];
        #pragma unroll
        for (int j = 0; j < 4; j++) {
            float t = acc[i][j] + bias4[j];
            if (RELU) t = fmaxf(t, 0.f);
            v[j] = t;
        }
        if (ADDK) {
            float kv[4];
            *(float4*)&kv[0] = *(const float4*)&addk[(long)m * N + n0 + nb];
            #pragma unroll
            for (int j = 0; j < 4; j++) v[j] += kv[j];
        }
        *(float4*)&C[(long)m * N + n0 + nb] = *(float4*)&v[0];
    }
}

// ---------------------------------------------------------------------------
// Launcher
// Input order (metadata): x, kg, idx, mask, Wkg, bkg, W1a,b1a, W1b,b1b,
//                         W1c,b1c, W1d,b1d, W2,b2.  Output: float [8192,1024].
// ---------------------------------------------------------------------------
extern "C" void kernel_launch(void* const* d_in, const int* in_sizes, int n_in,
                              void* d_out, int out_size)
{
    const float* x    = (const float*)d_in[0];
    const float* kg   = (const float*)d_in[1];
    const int*   idx  = (const int*)  d_in[2];
    const int*   mask = (const int*)  d_in[3];
    const float* Wkg  = (const float*)d_in[4];
    const float* bkg  = (const float*)d_in[5];
    const float* W1a  = (const float*)d_in[6];
    const float* b1a  = (const float*)d_in[7];
    const float* W1b  = (const float*)d_in[8];
    const float* b1b  = (const float*)d_in[9];
    const float* W1c  = (const float*)d_in[10];
    const float* b1c  = (const float*)d_in[11];
    const float* W1d  = (const float*)d_in[12];
    const float* b1d  = (const float*)d_in[13];
    const float* W2   = (const float*)d_in[14];
    const float* b2   = (const float*)d_in[15];
    float* out = (float*)d_out;

    float *h1, *h2, *h3, *h4, *know;
    int *cnt, *cidx;
    cudaGetSymbolAddress((void**)&h1,   g_h1);
    cudaGetSymbolAddress((void**)&h2,   g_h2);
    cudaGetSymbolAddress((void**)&h3,   g_h3);
    cudaGetSymbolAddress((void**)&h4,   g_h4);
    cudaGetSymbolAddress((void**)&know, g_know);
    cudaGetSymbolAddress((void**)&cnt,  g_cnt);
    cudaGetSymbolAddress((void**)&cidx, g_cidx);

    // knowledge branch
    compact_kernel<<<B_SZ / 8, 256>>>(idx, mask, cidx, cnt);
    knowledge_kernel<<<B_SZ / (4 * KB_PW), 256>>>(kg, Wkg, bkg, cidx, cnt, know);

    // dense MLP chain
    // L1a: [8192,512] @ [512,128]   -> BM=64 config (256 blocks)
    gemm_kernel<64, 32, 4, true, false><<<dim3(128 / 64, B_SZ / 64), 256>>>(
        x,  W1a, b1a, nullptr, h1, B_SZ, 128, IN_SZ);
    // L1b: [8192,128] @ [128,512]   -> BM=128 config (512 blocks)
    gemm_kernel<128, 16, 8, true, false><<<dim3(512 / 64, B_SZ / 128), 256>>>(
        h1, W1b, b1b, nullptr, h2, B_SZ, 512, 128);
    // L1c: [8192,512] @ [512,128]   -> BM=64 config
    gemm_kernel<64, 32, 4, true, false><<<dim3(128 / 64, B_SZ / 64), 256>>>(
        h2, W1c, b1c, nullptr, h3, B_SZ, 128, 512);
    // L1d: [8192,128] @ [128,64] + knowledge  (fused add)
    gemm_kernel<64, 32, 4, true, true><<<dim3(CC / 64, B_SZ / 64), 256>>>(
        h3, W1d, b1d, know, h4, B_SZ, CC, 128);
    // L2:  [8192,64] @ [64,1024]
    gemm_kernel<128, 16, 8, false, false><<<dim3(OUT_SZ / 64, B_SZ / 128), 256>>>(
        h4, W2, b2, nullptr, out, B_SZ, OUT_SZ, CC);
}